// round 1
// baseline (speedup 1.0000x reference)
#include <cuda_runtime.h>
#include <math.h>

#define N_POI 50000
#define DIM 128
#define E_EDGES 400000
#define GCN_NUM 3
#define BATCH 64
#define LSEQ 100
#define NTOK (BATCH*LSEQ)

// ---------------- device scratch (static, no allocations) ----------------
__device__ float g_dis[N_POI];                 // degree -> 1/sqrt(deg)
__device__ float g_w[E_EDGES];                 // per-undirected-edge weight
__device__ float g_bufA[N_POI*DIM];
__device__ float g_bufB[N_POI*DIM];
__device__ float g_agg[N_POI*DIM];
__device__ float g_qkv[NTOK*3*DIM];
__device__ float g_o[NTOK*DIM];

// ---------------- graph preprocessing ----------------
__global__ void k_deg_init(float* deg){
    int i = blockIdx.x*256 + threadIdx.x;
    if (i < N_POI) deg[i] = 1.0f;              // self-loop
}
__global__ void k_deg_count(const int* __restrict__ e0, const int* __restrict__ e1, float* deg){
    int e = blockIdx.x*256 + threadIdx.x;
    if (e < E_EDGES){
        atomicAdd(&deg[e0[e]], 1.0f);
        atomicAdd(&deg[e1[e]], 1.0f);
    }
}
__global__ void k_dis_fin(float* d){
    int i = blockIdx.x*256 + threadIdx.x;
    if (i < N_POI) d[i] = 1.0f / sqrtf(d[i]);  // deg >= 1 always
}
__global__ void k_edge_w(const float* __restrict__ dv, const int* __restrict__ e0,
                         const int* __restrict__ e1, const float* __restrict__ dis,
                         float* __restrict__ w){
    int e = blockIdx.x*256 + threadIdx.x;
    if (e < E_EDGES){
        float d = dv[e];
        w[e] = expf(-d*d) * dis[e0[e]] * dis[e1[e]];
    }
}

// ---------------- SpMM ----------------
// agg[i] = dis[i]^2 * enc[i]   (self-loop term, also initializes agg)
__global__ void k_selfloop(const float* __restrict__ enc, const float* __restrict__ dis,
                           float* __restrict__ agg){
    int i = blockIdx.x*256 + threadIdx.x;
    if (i < N_POI*DIM){
        int r = i >> 7;
        float ds = dis[r];
        agg[i] = ds*ds*enc[i];
    }
}
// one warp per undirected edge, scatter both directions with float4 reds
__global__ void k_spmm(const float* __restrict__ enc, const int* __restrict__ e0,
                       const int* __restrict__ e1, const float* __restrict__ w,
                       float* __restrict__ agg){
    int e = (blockIdx.x*blockDim.x + threadIdx.x) >> 5;
    int lane = threadIdx.x & 31;
    if (e >= E_EDGES) return;
    int a = e0[e], b = e1[e];
    float wv = w[e];
    const float4* encv = (const float4*)enc;
    float4* aggv = (float4*)agg;
    float4 xa = encv[a*32 + lane];
    float4 xb = encv[b*32 + lane];
    float4 ca = make_float4(wv*xb.x, wv*xb.y, wv*xb.z, wv*xb.w);
    float4 cb = make_float4(wv*xa.x, wv*xa.y, wv*xa.z, wv*xa.w);
    atomicAdd(&aggv[a*32 + lane], ca);   // sm_90+ vector atomic
    atomicAdd(&aggv[b*32 + lane], cb);
}

// ---------------- fused GEMM (Y = lrelu(X @ W^T + b), then row L2-normalize) ----------------
#define GN_ROWS 16
#define SHW_PITCH 129
__global__ void k_gemm_norm(const float* __restrict__ X, const float* __restrict__ W,
                            const float* __restrict__ bias, float* __restrict__ Y, int M){
    extern __shared__ float sh[];
    float* shW = sh;                         // [128][129] : shW[k*129+j] = W[j*128+k]
    float* shX = sh + DIM*SHW_PITCH;         // [16][128]
    int tid = threadIdx.x;
    for (int idx = tid; idx < DIM*DIM; idx += 128){
        int j = idx >> 7, k = idx & 127;
        shW[k*SHW_PITCH + j] = W[idx];
    }
    int row0 = blockIdx.x * GN_ROWS;
    for (int idx = tid; idx < GN_ROWS*DIM; idx += 128){
        int r = idx >> 7, k = idx & 127;
        int row = row0 + r;
        shX[idx] = (row < M) ? X[row*DIM + k] : 0.0f;
    }
    __syncthreads();

    float acc[GN_ROWS];
    #pragma unroll
    for (int r = 0; r < GN_ROWS; r++) acc[r] = 0.0f;
    #pragma unroll 4
    for (int k = 0; k < DIM; k++){
        float wv = shW[k*SHW_PITCH + tid];
        #pragma unroll
        for (int r = 0; r < GN_ROWS; r++) acc[r] += shX[r*DIM + k] * wv;
    }

    __shared__ float sred[GN_ROWS][4];
    __shared__ float sscale[GN_ROWS];
    int lane = tid & 31, warp = tid >> 5;
    float bj = bias[tid];
    #pragma unroll
    for (int r = 0; r < GN_ROWS; r++){
        float v = acc[r] + bj;
        v = (v >= 0.0f) ? v : 0.01f*v;
        acc[r] = v;
        float ss = v*v;
        #pragma unroll
        for (int o = 16; o > 0; o >>= 1) ss += __shfl_xor_sync(0xffffffffu, ss, o);
        if (lane == 0) sred[r][warp] = ss;
    }
    __syncthreads();
    if (tid < GN_ROWS){
        float ss = sred[tid][0] + sred[tid][1] + sred[tid][2] + sred[tid][3];
        float n = fmaxf(sqrtf(ss), 1e-12f);
        sscale[tid] = 1.0f / n;
    }
    __syncthreads();
    #pragma unroll
    for (int r = 0; r < GN_ROWS; r++){
        int row = row0 + r;
        if (row < M) Y[row*DIM + tid] = acc[r] * sscale[r];
    }
}

// ---------------- QKV projection (gathered input), 16 tokens/block ----------------
__global__ void k_qkv(const float* __restrict__ enc, const int* __restrict__ xidx,
                      const float* __restrict__ inw, const float* __restrict__ inb,
                      float* __restrict__ qkv){
    extern __shared__ float sh[];
    float* shW = sh;
    float* shX = sh + DIM*SHW_PITCH;
    int tid = threadIdx.x;
    int t0 = blockIdx.x * GN_ROWS;
    for (int idx = tid; idx < GN_ROWS*DIM; idx += 128){
        int r = idx >> 7, k = idx & 127;
        shX[idx] = enc[xidx[t0 + r]*DIM + k];
    }
    for (int c = 0; c < 3; c++){
        __syncthreads();
        for (int idx = tid; idx < DIM*DIM; idx += 128){
            int j = idx >> 7, k = idx & 127;
            shW[k*SHW_PITCH + j] = inw[c*DIM*DIM + idx];
        }
        __syncthreads();
        float acc[GN_ROWS];
        #pragma unroll
        for (int r = 0; r < GN_ROWS; r++) acc[r] = 0.0f;
        #pragma unroll 4
        for (int k = 0; k < DIM; k++){
            float wv = shW[k*SHW_PITCH + tid];
            #pragma unroll
            for (int r = 0; r < GN_ROWS; r++) acc[r] += shX[r*DIM + k] * wv;
        }
        float bj = inb[c*DIM + tid];
        #pragma unroll
        for (int r = 0; r < GN_ROWS; r++)
            qkv[(t0 + r)*(3*DIM) + c*DIM + tid] = acc[r] + bj;
    }
}

// ---------------- attention: one block per (b, h) ----------------
__global__ void k_attn(const float* __restrict__ qkv, float* __restrict__ o){
    __shared__ float sq[LSEQ*16], sk[LSEQ*16], sv[LSEQ*16];
    __shared__ float sp[32*LSEQ];
    int b = blockIdx.x, h = blockIdx.y;
    int tid = threadIdx.x;
    for (int idx = tid; idx < LSEQ*16; idx += 128){
        int t = idx >> 4, d = idx & 15;
        int base = (b*LSEQ + t)*(3*DIM) + h*16 + d;
        sq[idx] = qkv[base];
        sk[idx] = qkv[base + DIM];
        sv[idx] = qkv[base + 2*DIM];
    }
    __syncthreads();
    int lane = tid & 31, warp = tid >> 5;
    for (int q0 = 0; q0 < LSEQ; q0 += 32){
        int nq = min(32, LSEQ - q0);
        for (int idx = tid; idx < nq*LSEQ; idx += 128){
            int qi = idx / LSEQ, j = idx - qi*LSEQ;
            const float* qp = &sq[(q0 + qi)*16];
            const float* kp = &sk[j*16];
            float s = 0.0f;
            #pragma unroll
            for (int d = 0; d < 16; d++) s += qp[d]*kp[d];
            sp[idx] = s*0.25f;   // 1/sqrt(16)
        }
        __syncthreads();
        for (int qi = warp; qi < nq; qi += 4){
            float v[4];
            float m = -1e30f;
            #pragma unroll
            for (int jj = 0; jj < 4; jj++){
                int j = lane + jj*32;
                v[jj] = (j < LSEQ) ? sp[qi*LSEQ + j] : -1e30f;
                m = fmaxf(m, v[jj]);
            }
            #pragma unroll
            for (int t = 16; t > 0; t >>= 1) m = fmaxf(m, __shfl_xor_sync(0xffffffffu, m, t));
            float s = 0.0f;
            #pragma unroll
            for (int jj = 0; jj < 4; jj++){
                int j = lane + jj*32;
                float p = (j < LSEQ) ? expf(v[jj] - m) : 0.0f;
                v[jj] = p; s += p;
            }
            #pragma unroll
            for (int t = 16; t > 0; t >>= 1) s += __shfl_xor_sync(0xffffffffu, s, t);
            float inv = 1.0f / s;
            #pragma unroll
            for (int jj = 0; jj < 4; jj++){
                int j = lane + jj*32;
                if (j < LSEQ) sp[qi*LSEQ + j] = v[jj]*inv;
            }
        }
        __syncthreads();
        for (int idx = tid; idx < nq*16; idx += 128){
            int qi = idx >> 4, d = idx & 15;
            float acc = 0.0f;
            for (int j = 0; j < LSEQ; j++) acc += sp[qi*LSEQ + j]*sv[j*16 + d];
            o[(b*LSEQ + q0 + qi)*DIM + h*16 + d] = acc;
        }
        __syncthreads();
    }
}

// ---------------- mean over L then out-projection (they commute) ----------------
__global__ void k_mean_proj(const float* __restrict__ o, const float* __restrict__ ow,
                            const float* __restrict__ ob, float* __restrict__ out){
    __shared__ float sx[DIM];
    int b = blockIdx.x, j = threadIdx.x;
    float s = 0.0f;
    for (int i = 0; i < LSEQ; i++) s += o[(b*LSEQ + i)*DIM + j];
    sx[j] = s * (1.0f/LSEQ);
    __syncthreads();
    float acc = ob[j];
    #pragma unroll 4
    for (int k = 0; k < DIM; k++) acc += sx[k]*ow[j*DIM + k];
    out[b*DIM + j] = acc;
}

__global__ void k_tar(const float* __restrict__ enc, const int* __restrict__ pidx,
                      float* __restrict__ out){
    int b = blockIdx.x, j = threadIdx.x;
    out[BATCH*DIM + b*DIM + j] = enc[pidx[b]*DIM + j];
}

// ---------------- host launch ----------------
extern "C" void kernel_launch(void* const* d_in, const int* in_sizes, int n_in,
                              void* d_out, int out_size){
    const float* embeds = (const float*)d_in[0];
    const float* gcnW   = (const float*)d_in[1];
    const float* gcnb   = (const float*)d_in[2];
    const float* inw    = (const float*)d_in[3];
    const float* inb    = (const float*)d_in[4];
    const float* ow     = (const float*)d_in[5];
    const float* ob     = (const float*)d_in[6];
    const float* dv     = (const float*)d_in[7];
    const int*   edges  = (const int*)d_in[8];
    const int*   xidx   = (const int*)d_in[9];
    const int*   pidx   = (const int*)d_in[10];
    const int* e0 = edges;
    const int* e1 = edges + E_EDGES;
    float* out = (float*)d_out;

    float *dis, *w, *agg, *bA, *bB, *qkv, *obuf;
    cudaGetSymbolAddress((void**)&dis,  g_dis);
    cudaGetSymbolAddress((void**)&w,    g_w);
    cudaGetSymbolAddress((void**)&agg,  g_agg);
    cudaGetSymbolAddress((void**)&bA,   g_bufA);
    cudaGetSymbolAddress((void**)&bB,   g_bufB);
    cudaGetSymbolAddress((void**)&qkv,  g_qkv);
    cudaGetSymbolAddress((void**)&obuf, g_o);

    const int smem_gemm = (DIM*SHW_PITCH + GN_ROWS*DIM)*(int)sizeof(float);  // 74240
    cudaFuncSetAttribute(k_gemm_norm, cudaFuncAttributeMaxDynamicSharedMemorySize, smem_gemm);
    cudaFuncSetAttribute(k_qkv,       cudaFuncAttributeMaxDynamicSharedMemorySize, smem_gemm);

    // graph preprocessing
    k_deg_init<<<(N_POI+255)/256, 256>>>(dis);
    k_deg_count<<<(E_EDGES+255)/256, 256>>>(e0, e1, dis);
    k_dis_fin<<<(N_POI+255)/256, 256>>>(dis);
    k_edge_w<<<(E_EDGES+255)/256, 256>>>(dv, e0, e1, dis, w);

    // 3 GCN layers
    const float* enc_in = embeds;
    float* outs[GCN_NUM] = {bA, bB, bA};
    for (int i = 0; i < GCN_NUM; i++){
        k_selfloop<<<(N_POI*DIM+255)/256, 256>>>(enc_in, dis, agg);
        k_spmm<<<(E_EDGES+7)/8, 256>>>(enc_in, e0, e1, w, agg);
        k_gemm_norm<<<(N_POI+GN_ROWS-1)/GN_ROWS, 128, smem_gemm>>>(
            agg, gcnW + i*DIM*DIM, gcnb + i*DIM, outs[i], N_POI);
        enc_in = outs[i];
    }
    const float* encF = enc_in;  // g_bufA

    // attention
    k_qkv<<<NTOK/GN_ROWS, 128, smem_gemm>>>(encF, xidx, inw, inb, qkv);
    k_attn<<<dim3(BATCH, 8), 128>>>(qkv, obuf);
    k_mean_proj<<<BATCH, 128>>>(obuf, ow, ob, out);
    k_tar<<<BATCH, 128>>>(encF, pidx, out);
}

// round 2
// speedup vs baseline: 2.0249x; 2.0249x over previous
#include <cuda_runtime.h>
#include <math.h>

#define N_POI 50000
#define DIM 128
#define E_EDGES 400000
#define GCN_NUM 3
#define BATCH 64
#define LSEQ 100
#define NTOK (BATCH*LSEQ)
#define DIRE (2*E_EDGES)

// ---------------- device scratch (static, no allocations) ----------------
__device__ __align__(16) int   g_cnt[N_POI];
__device__ __align__(16) int   g_rowptr[N_POI+1];
__device__ __align__(16) int   g_rowcur[N_POI];
__device__ __align__(16) float g_dis[N_POI];
__device__ __align__(16) int   g_colidx[DIRE];
__device__ __align__(16) float g_wcsr[DIRE];
__device__ __align__(16) float g_bufA[N_POI*DIM];
__device__ __align__(16) float g_bufB[N_POI*DIM];
__device__ __align__(16) float g_agg[N_POI*DIM];
__device__ __align__(16) float g_qkv[NTOK*3*DIM];
__device__ __align__(16) float g_o[NTOK*DIM];

// ---------------- CSR build ----------------
__global__ void k_zero_cnt(int* cnt){
    int i = blockIdx.x*256 + threadIdx.x;
    if (i < N_POI) cnt[i] = 0;
}
__global__ void k_hist(const int* __restrict__ e0, const int* __restrict__ e1, int* cnt){
    int e = blockIdx.x*256 + threadIdx.x;
    if (e < E_EDGES){
        atomicAdd(&cnt[e0[e]], 1);
        atomicAdd(&cnt[e1[e]], 1);
    }
}
// single-block exclusive scan over 50k counts
__global__ void k_scan(const int* __restrict__ cnt, int* __restrict__ rowptr,
                       int* __restrict__ rowcur){
    __shared__ int sh[1024];
    int t = threadIdx.x;
    const int CH = (N_POI + 1023)/1024;   // 49
    int base = t*CH;
    int s = 0;
    for (int i = 0; i < CH; i++){
        int idx = base + i;
        if (idx < N_POI) s += cnt[idx];
    }
    sh[t] = s;
    __syncthreads();
    for (int o = 1; o < 1024; o <<= 1){
        int v = (t >= o) ? sh[t-o] : 0;
        __syncthreads();
        sh[t] += v;
        __syncthreads();
    }
    int off = (t == 0) ? 0 : sh[t-1];
    for (int i = 0; i < CH; i++){
        int idx = base + i;
        if (idx < N_POI){
            rowptr[idx] = off;
            rowcur[idx] = off;
            off += cnt[idx];
        }
    }
    if (t == 1023) rowptr[N_POI] = sh[1023];
}
__global__ void k_dis(const int* __restrict__ cnt, float* __restrict__ dis){
    int i = blockIdx.x*256 + threadIdx.x;
    if (i < N_POI) dis[i] = rsqrtf((float)(cnt[i] + 1));   // +1 self-loop
}
__global__ void k_scatter(const int* __restrict__ e0, const int* __restrict__ e1,
                          const float* __restrict__ dv, const float* __restrict__ dis,
                          int* rowcur, int* __restrict__ colidx, float* __restrict__ wcsr){
    int e = blockIdx.x*256 + threadIdx.x;
    if (e >= E_EDGES) return;
    int a = e0[e], b = e1[e];
    float d = dv[e];
    float wv = expf(-d*d) * dis[a] * dis[b];
    int p = atomicAdd(&rowcur[a], 1);
    colidx[p] = b; wcsr[p] = wv;
    p = atomicAdd(&rowcur[b], 1);
    colidx[p] = a; wcsr[p] = wv;
}

// ---------------- SpMM: per-row gather (one warp per row), self-loop fused ----------------
__global__ void k_spmm2(const float4* __restrict__ enc4, const int* __restrict__ rowptr,
                        const int* __restrict__ cols, const float* __restrict__ ws,
                        const float* __restrict__ dis, float4* __restrict__ agg4){
    int row = blockIdx.x*8 + (threadIdx.x >> 5);
    int lane = threadIdx.x & 31;
    if (row >= N_POI) return;
    float ds = dis[row];
    float4 x = enc4[row*32 + lane];
    float sl = ds*ds;
    float4 acc = make_float4(sl*x.x, sl*x.y, sl*x.z, sl*x.w);
    int s = __ldg(&rowptr[row]), e = __ldg(&rowptr[row+1]);
    int i = s;
    for (; i + 4 <= e; i += 4){
        int c0 = __ldg(&cols[i]),   c1 = __ldg(&cols[i+1]);
        int c2 = __ldg(&cols[i+2]), c3 = __ldg(&cols[i+3]);
        float w0 = __ldg(&ws[i]),   w1 = __ldg(&ws[i+1]);
        float w2 = __ldg(&ws[i+2]), w3 = __ldg(&ws[i+3]);
        float4 v0 = enc4[c0*32 + lane];
        float4 v1 = enc4[c1*32 + lane];
        float4 v2 = enc4[c2*32 + lane];
        float4 v3 = enc4[c3*32 + lane];
        acc.x = fmaf(w3,v3.x, fmaf(w2,v2.x, fmaf(w1,v1.x, fmaf(w0,v0.x, acc.x))));
        acc.y = fmaf(w3,v3.y, fmaf(w2,v2.y, fmaf(w1,v1.y, fmaf(w0,v0.y, acc.y))));
        acc.z = fmaf(w3,v3.z, fmaf(w2,v2.z, fmaf(w1,v1.z, fmaf(w0,v0.z, acc.z))));
        acc.w = fmaf(w3,v3.w, fmaf(w2,v2.w, fmaf(w1,v1.w, fmaf(w0,v0.w, acc.w))));
    }
    for (; i < e; i++){
        int c = __ldg(&cols[i]);
        float wv = __ldg(&ws[i]);
        float4 v = enc4[c*32 + lane];
        acc.x = fmaf(wv, v.x, acc.x);
        acc.y = fmaf(wv, v.y, acc.y);
        acc.z = fmaf(wv, v.z, acc.z);
        acc.w = fmaf(wv, v.w, acc.w);
    }
    agg4[row*32 + lane] = acc;
}

// ---------------- tiled SGEMM 128x128 tile, 8x8 microtile ----------------
// Y = rownorm(lrelu(X @ W^T + b));  K = 128 (whole reduction in one tile)
__global__ void __launch_bounds__(256, 1)
k_gemm_norm2(const float4* __restrict__ X4, const float* __restrict__ W,
             const float* __restrict__ bias, float4* __restrict__ Y4, int M){
    extern __shared__ float4 sh4[];
    float4* Xs = sh4;            // [128][32]  Xs[m*32 + k4]
    float4* Ws = sh4 + 4096;     // [128][32]  Ws[n*32 + (k4 ^ (n>>3))]
    int tid = threadIdx.x;
    int row0 = blockIdx.x * 128;
    const float4 z4 = make_float4(0.f,0.f,0.f,0.f);
    #pragma unroll
    for (int it = 0; it < 16; it++){
        int idx = tid + it*256;
        int m = idx >> 5, k4 = idx & 31;
        int row = row0 + m;
        Xs[idx] = (row < M) ? X4[row*32 + k4] : z4;
    }
    const float4* W4 = (const float4*)W;
    #pragma unroll
    for (int it = 0; it < 16; it++){
        int idx = tid + it*256;
        int n = idx >> 5, k4 = idx & 31;
        Ws[n*32 + (k4 ^ (n >> 3))] = W4[idx];
    }
    __syncthreads();

    int tx = tid & 15, ty = tid >> 4;
    float acc[8][8];
    #pragma unroll
    for (int r = 0; r < 8; r++)
        #pragma unroll
        for (int c = 0; c < 8; c++) acc[r][c] = 0.f;

    const float4* Xp = Xs + (ty*8)*32;
    const float4* Wp = Ws + (tx*8)*32;
    #pragma unroll 2
    for (int k4 = 0; k4 < 32; k4++){
        float4 xv[8], wv[8];
        #pragma unroll
        for (int r = 0; r < 8; r++) xv[r] = Xp[r*32 + k4];
        int ksw = k4 ^ tx;
        #pragma unroll
        for (int c = 0; c < 8; c++) wv[c] = Wp[c*32 + ksw];
        #pragma unroll
        for (int r = 0; r < 8; r++)
            #pragma unroll
            for (int c = 0; c < 8; c++){
                acc[r][c] = fmaf(xv[r].x, wv[c].x, acc[r][c]);
                acc[r][c] = fmaf(xv[r].y, wv[c].y, acc[r][c]);
                acc[r][c] = fmaf(xv[r].z, wv[c].z, acc[r][c]);
                acc[r][c] = fmaf(xv[r].w, wv[c].w, acc[r][c]);
            }
    }

    float bj[8];
    #pragma unroll
    for (int c = 0; c < 8; c++) bj[c] = __ldg(&bias[tx*8 + c]);
    #pragma unroll
    for (int r = 0; r < 8; r++){
        float ss = 0.f;
        #pragma unroll
        for (int c = 0; c < 8; c++){
            float v = acc[r][c] + bj[c];
            v = (v >= 0.f) ? v : 0.01f*v;
            acc[r][c] = v;
            ss = fmaf(v, v, ss);
        }
        #pragma unroll
        for (int o = 8; o > 0; o >>= 1) ss += __shfl_xor_sync(0xffffffffu, ss, o);
        float inv = 1.0f / fmaxf(sqrtf(ss), 1e-12f);
        int row = row0 + ty*8 + r;
        if (row < M){
            Y4[row*32 + tx*2]     = make_float4(acc[r][0]*inv, acc[r][1]*inv, acc[r][2]*inv, acc[r][3]*inv);
            Y4[row*32 + tx*2 + 1] = make_float4(acc[r][4]*inv, acc[r][5]*inv, acc[r][6]*inv, acc[r][7]*inv);
        }
    }
}

// ---------------- QKV: same tiled GEMM, gathered rows, no norm ----------------
// grid.x = NTOK/128 (=50), grid.y = 3 (q/k/v chunk)
__global__ void __launch_bounds__(256, 1)
k_qkv2(const float4* __restrict__ enc4, const int* __restrict__ xidx,
       const float* __restrict__ inw, const float* __restrict__ inb,
       float4* __restrict__ qkv4){
    extern __shared__ float4 sh4[];
    float4* Xs = sh4;
    float4* Ws = sh4 + 4096;
    int tid = threadIdx.x;
    int row0 = blockIdx.x * 128;
    int nb = blockIdx.y;
    #pragma unroll
    for (int it = 0; it < 16; it++){
        int idx = tid + it*256;
        int m = idx >> 5, k4 = idx & 31;
        int src = __ldg(&xidx[row0 + m]);
        Xs[idx] = enc4[src*32 + k4];
    }
    const float4* W4 = (const float4*)(inw + nb*DIM*DIM);
    #pragma unroll
    for (int it = 0; it < 16; it++){
        int idx = tid + it*256;
        int n = idx >> 5, k4 = idx & 31;
        Ws[n*32 + (k4 ^ (n >> 3))] = W4[idx];
    }
    __syncthreads();

    int tx = tid & 15, ty = tid >> 4;
    float acc[8][8];
    #pragma unroll
    for (int r = 0; r < 8; r++)
        #pragma unroll
        for (int c = 0; c < 8; c++) acc[r][c] = 0.f;

    const float4* Xp = Xs + (ty*8)*32;
    const float4* Wp = Ws + (tx*8)*32;
    #pragma unroll 2
    for (int k4 = 0; k4 < 32; k4++){
        float4 xv[8], wv[8];
        #pragma unroll
        for (int r = 0; r < 8; r++) xv[r] = Xp[r*32 + k4];
        int ksw = k4 ^ tx;
        #pragma unroll
        for (int c = 0; c < 8; c++) wv[c] = Wp[c*32 + ksw];
        #pragma unroll
        for (int r = 0; r < 8; r++)
            #pragma unroll
            for (int c = 0; c < 8; c++){
                acc[r][c] = fmaf(xv[r].x, wv[c].x, acc[r][c]);
                acc[r][c] = fmaf(xv[r].y, wv[c].y, acc[r][c]);
                acc[r][c] = fmaf(xv[r].z, wv[c].z, acc[r][c]);
                acc[r][c] = fmaf(xv[r].w, wv[c].w, acc[r][c]);
            }
    }

    float bj[8];
    #pragma unroll
    for (int c = 0; c < 8; c++) bj[c] = __ldg(&inb[nb*DIM + tx*8 + c]);
    #pragma unroll
    for (int r = 0; r < 8; r++){
        int t = row0 + ty*8 + r;
        qkv4[t*96 + nb*32 + tx*2]     = make_float4(acc[r][0]+bj[0], acc[r][1]+bj[1], acc[r][2]+bj[2], acc[r][3]+bj[3]);
        qkv4[t*96 + nb*32 + tx*2 + 1] = make_float4(acc[r][4]+bj[4], acc[r][5]+bj[5], acc[r][6]+bj[6], acc[r][7]+bj[7]);
    }
}

// ---------------- attention: one block per (b, h) ----------------
__global__ void k_attn(const float* __restrict__ qkv, float* __restrict__ o){
    __shared__ float sq[LSEQ*16], sk[LSEQ*16], sv[LSEQ*16];
    __shared__ float sp[32*LSEQ];
    int b = blockIdx.x, h = blockIdx.y;
    int tid = threadIdx.x;
    for (int idx = tid; idx < LSEQ*16; idx += 128){
        int t = idx >> 4, d = idx & 15;
        int base = (b*LSEQ + t)*(3*DIM) + h*16 + d;
        sq[idx] = qkv[base];
        sk[idx] = qkv[base + DIM];
        sv[idx] = qkv[base + 2*DIM];
    }
    __syncthreads();
    int lane = tid & 31, warp = tid >> 5;
    for (int q0 = 0; q0 < LSEQ; q0 += 32){
        int nq = min(32, LSEQ - q0);
        for (int idx = tid; idx < nq*LSEQ; idx += 128){
            int qi = idx / LSEQ, j = idx - qi*LSEQ;
            const float* qp = &sq[(q0 + qi)*16];
            const float* kp = &sk[j*16];
            float s = 0.0f;
            #pragma unroll
            for (int d = 0; d < 16; d++) s += qp[d]*kp[d];
            sp[idx] = s*0.25f;   // 1/sqrt(16)
        }
        __syncthreads();
        for (int qi = warp; qi < nq; qi += 4){
            float v[4];
            float m = -1e30f;
            #pragma unroll
            for (int jj = 0; jj < 4; jj++){
                int j = lane + jj*32;
                v[jj] = (j < LSEQ) ? sp[qi*LSEQ + j] : -1e30f;
                m = fmaxf(m, v[jj]);
            }
            #pragma unroll
            for (int t = 16; t > 0; t >>= 1) m = fmaxf(m, __shfl_xor_sync(0xffffffffu, m, t));
            float s = 0.0f;
            #pragma unroll
            for (int jj = 0; jj < 4; jj++){
                int j = lane + jj*32;
                float p = (j < LSEQ) ? expf(v[jj] - m) : 0.0f;
                v[jj] = p; s += p;
            }
            #pragma unroll
            for (int t = 16; t > 0; t >>= 1) s += __shfl_xor_sync(0xffffffffu, s, t);
            float inv = 1.0f / s;
            #pragma unroll
            for (int jj = 0; jj < 4; jj++){
                int j = lane + jj*32;
                if (j < LSEQ) sp[qi*LSEQ + j] = v[jj]*inv;
            }
        }
        __syncthreads();
        for (int idx = tid; idx < nq*16; idx += 128){
            int qi = idx >> 4, d = idx & 15;
            float acc = 0.0f;
            for (int j = 0; j < LSEQ; j++) acc += sp[qi*LSEQ + j]*sv[j*16 + d];
            o[(b*LSEQ + q0 + qi)*DIM + h*16 + d] = acc;
        }
        __syncthreads();
    }
}

// ---------------- mean over L then out-projection (they commute) ----------------
__global__ void k_mean_proj(const float* __restrict__ o, const float* __restrict__ ow,
                            const float* __restrict__ ob, float* __restrict__ out){
    __shared__ float sx[DIM];
    int b = blockIdx.x, j = threadIdx.x;
    float s = 0.0f;
    for (int i = 0; i < LSEQ; i++) s += o[(b*LSEQ + i)*DIM + j];
    sx[j] = s * (1.0f/LSEQ);
    __syncthreads();
    float acc = ob[j];
    #pragma unroll 4
    for (int k = 0; k < DIM; k++) acc += sx[k]*ow[j*DIM + k];
    out[b*DIM + j] = acc;
}

__global__ void k_tar(const float* __restrict__ enc, const int* __restrict__ pidx,
                      float* __restrict__ out){
    int b = blockIdx.x, j = threadIdx.x;
    out[BATCH*DIM + b*DIM + j] = enc[pidx[b]*DIM + j];
}

// ---------------- host launch ----------------
extern "C" void kernel_launch(void* const* d_in, const int* in_sizes, int n_in,
                              void* d_out, int out_size){
    const float* embeds = (const float*)d_in[0];
    const float* gcnW   = (const float*)d_in[1];
    const float* gcnb   = (const float*)d_in[2];
    const float* inw    = (const float*)d_in[3];
    const float* inb    = (const float*)d_in[4];
    const float* ow     = (const float*)d_in[5];
    const float* ob     = (const float*)d_in[6];
    const float* dv     = (const float*)d_in[7];
    const int*   edges  = (const int*)d_in[8];
    const int*   xidx   = (const int*)d_in[9];
    const int*   pidx   = (const int*)d_in[10];
    const int* e0 = edges;
    const int* e1 = edges + E_EDGES;
    float* out = (float*)d_out;

    int *cnt, *rowptr, *rowcur, *colidx;
    float *dis, *wcsr, *agg, *bA, *bB, *qkv, *obuf;
    cudaGetSymbolAddress((void**)&cnt,    g_cnt);
    cudaGetSymbolAddress((void**)&rowptr, g_rowptr);
    cudaGetSymbolAddress((void**)&rowcur, g_rowcur);
    cudaGetSymbolAddress((void**)&dis,    g_dis);
    cudaGetSymbolAddress((void**)&colidx, g_colidx);
    cudaGetSymbolAddress((void**)&wcsr,   g_wcsr);
    cudaGetSymbolAddress((void**)&agg,    g_agg);
    cudaGetSymbolAddress((void**)&bA,     g_bufA);
    cudaGetSymbolAddress((void**)&bB,     g_bufB);
    cudaGetSymbolAddress((void**)&qkv,    g_qkv);
    cudaGetSymbolAddress((void**)&obuf,   g_o);

    const int smem_gemm = 2*4096*(int)sizeof(float4);   // 131072
    static int cfg_done = 0;
    cudaFuncSetAttribute(k_gemm_norm2, cudaFuncAttributeMaxDynamicSharedMemorySize, smem_gemm);
    cudaFuncSetAttribute(k_qkv2,       cudaFuncAttributeMaxDynamicSharedMemorySize, smem_gemm);
    (void)cfg_done;

    // CSR build (runs inside the graph every replay; ~O(E), cheap)
    k_zero_cnt<<<(N_POI+255)/256, 256>>>(cnt);
    k_hist<<<(E_EDGES+255)/256, 256>>>(e0, e1, cnt);
    k_scan<<<1, 1024>>>(cnt, rowptr, rowcur);
    k_dis<<<(N_POI+255)/256, 256>>>(cnt, dis);
    k_scatter<<<(E_EDGES+255)/256, 256>>>(e0, e1, dv, dis, rowcur, colidx, wcsr);

    // 3 GCN layers
    const float* enc_in = embeds;
    float* outs[GCN_NUM] = {bA, bB, bA};
    for (int i = 0; i < GCN_NUM; i++){
        k_spmm2<<<(N_POI+7)/8, 256>>>((const float4*)enc_in, rowptr, colidx, wcsr, dis,
                                       (float4*)agg);
        k_gemm_norm2<<<(N_POI+127)/128, 256, smem_gemm>>>(
            (const float4*)agg, gcnW + i*DIM*DIM, gcnb + i*DIM, (float4*)outs[i], N_POI);
        enc_in = outs[i];
    }
    const float* encF = enc_in;  // g_bufA

    // attention
    k_qkv2<<<dim3(NTOK/128, 3), 256, smem_gemm>>>((const float4*)encF, xidx, inw, inb,
                                                  (float4*)qkv);
    k_attn<<<dim3(BATCH, 8), 128>>>(qkv, obuf);
    k_mean_proj<<<BATCH, 128>>>(obuf, ow, ob, out);
    k_tar<<<BATCH, 128>>>(encF, pidx, out);
}